// round 15
// baseline (speedup 1.0000x reference)
#include <cuda_runtime.h>
#include <cuda_bf16.h>
#include <math.h>

#define T_TOK 8192
#define DD    128
#define MM    64
#define GROUPS 5
#define NMG   13          // mechanisms per group (5*13 = 65)

typedef unsigned long long ull;
typedef unsigned int u32;
typedef unsigned short u16;

// ---------------- scratch ----------------------------------------------------
__device__ float g_cbuf[T_TOK * MM];        // c[t][m]
__device__ float g_uT[DD * MM];             // [d][m]
__device__ float g_bveff[MM];
__device__ float g_bc[MM * DD];             // bt + char
__device__ float g_bct[65 * DD];            // bctil[m] ; m=64 -> bi
__device__ u32   g_Bpk[65 * 16384];         // kc W frag-packed
__device__ u32   g_W1pk[16 * 48 * 32 * 4];  // kb extended-W frag-packed (384 cols)
__device__ float g_hta[(size_t)T_TOK * 384];// kb1 output: gelu(h) | timing | victory
__device__ float g_part[GROUPS * T_TOK * DD];
__device__ u16   g_xchi[(size_t)T_TOK * 256];  // concat(x,ctx) bf16 hi
__device__ u16   g_xclo[(size_t)T_TOK * 256];  // concat(x,ctx) bf16 lo

// ---------------- helpers ------------------------------------------------------
__device__ __forceinline__ u32 smem_u32(const void* p) {
    u32 a;
    asm("{ .reg .u64 t; cvta.to.shared.u64 t, %1; cvt.u32.u64 %0, t; }" : "=r"(a) : "l"(p));
    return a;
}
__device__ __forceinline__ void mma_bf16(float* c, const u32* a, const u32* b) {
    asm volatile("mma.sync.aligned.m16n8k16.row.col.f32.bf16.bf16.f32 "
        "{%0,%1,%2,%3}, {%4,%5,%6,%7}, {%8,%9}, {%0,%1,%2,%3};"
        : "+f"(c[0]), "+f"(c[1]), "+f"(c[2]), "+f"(c[3])
        : "r"(a[0]), "r"(a[1]), "r"(a[2]), "r"(a[3]), "r"(b[0]), "r"(b[1]));
}
__device__ __forceinline__ void ldsm4(u32* r, u32 addr) {
    asm volatile("ldmatrix.sync.aligned.m8n8.x4.shared.b16 {%0,%1,%2,%3}, [%4];"
        : "=r"(r[0]), "=r"(r[1]), "=r"(r[2]), "=r"(r[3]) : "r"(addr));
}
__device__ __forceinline__ void lds128(u32* r, u32 addr) {
    asm volatile("ld.shared.v4.u32 {%0,%1,%2,%3}, [%4];"
        : "=r"(r[0]), "=r"(r[1]), "=r"(r[2]), "=r"(r[3]) : "r"(addr));
}
__device__ __forceinline__ void cp16(u32 dst, const void* src) {
    asm volatile("cp.async.cg.shared.global [%0], [%1], 16;" :: "r"(dst), "l"(src) : "memory");
}
__device__ __forceinline__ void split_bf16(float v, u16& h, u16& l) {
    __nv_bfloat16 hb = __float2bfloat16_rn(v);
    float r = v - __bfloat162float(hb);
    h = __bfloat16_as_ushort(hb);
    l = __bfloat16_as_ushort(__float2bfloat16_rn(r));
}

// ---------------- kx: split concat(x,ctx) to bf16 hi/lo global images ----------
__global__ void __launch_bounds__(256) kx_split(
    const float* __restrict__ x, const float* __restrict__ ctx)
{
    int idx = blockIdx.x * 256 + threadIdx.x;   // float4 id over [T_TOK][64]
    int tok = idx >> 6, cq = idx & 63;
    float4 v = (cq < 32) ? ((const float4*)(x   + (size_t)tok * DD))[cq]
                         : ((const float4*)(ctx + (size_t)tok * DD))[cq - 32];
    u16 h[4], l[4];
    split_bf16(v.x, h[0], l[0]); split_bf16(v.y, h[1], l[1]);
    split_bf16(v.z, h[2], l[2]); split_bf16(v.w, h[3], l[3]);
    size_t o = (size_t)tok * 256 + cq * 4;
    *(uint2*)&g_xchi[o] = make_uint2((u32)h[0] | ((u32)h[1] << 16), (u32)h[2] | ((u32)h[3] << 16));
    *(uint2*)&g_xclo[o] = make_uint2((u32)l[0] | ((u32)l[1] << 16), (u32)l[2] | ((u32)l[3] << 16));
}

// ---------------- ka1: bc, bveff, uT --------------------------------------------
__global__ void __launch_bounds__(128) ka1(
    const float* __restrict__ Wt, const float* __restrict__ bt,
    const float* __restrict__ chr,
    const float* __restrict__ Wv, const float* __restrict__ bv)
{
    int m = blockIdx.x, tid = threadIdx.x;
    int lane = tid & 31, warp = tid >> 5;
    __shared__ float red[4];

    float wv  = Wv[m * DD + tid];
    float bcv = bt[m * DD + tid] + chr[m * DD + tid];
    g_bc[m * DD + tid]  = bcv;

    float v = bcv * wv;
    #pragma unroll
    for (int o = 16; o > 0; o >>= 1) v += __shfl_down_sync(0xffffffffu, v, o);
    if (lane == 0) red[warp] = v;
    __syncthreads();
    if (tid == 0) g_bveff[m] = bv[m] + red[0] + red[1] + red[2] + red[3];

    const float4* W4 = (const float4*)Wt + (size_t)m * 4096;
    float4 wv4 = ((const float4*)(Wv + m * DD))[lane];
    for (int r = warp; r < DD; r += 8) {
        float4 w0 = W4[r * 32 + lane];
        float4 w1 = W4[(r + 4) * 32 + lane];
        float a0 = w0.x * wv4.x + w0.y * wv4.y + w0.z * wv4.z + w0.w * wv4.w;
        float a1 = w1.x * wv4.x + w1.y * wv4.y + w1.z * wv4.z + w1.w * wv4.w;
        #pragma unroll
        for (int o = 16; o > 0; o >>= 1) {
            a0 += __shfl_down_sync(0xffffffffu, a0, o);
            a1 += __shfl_down_sync(0xffffffffu, a1, o);
        }
        if (lane == 0) {
            g_uT[r * MM + m]       = a0;
            g_uT[(r + 4) * MM + m] = a1;
        }
    }
}

// ---------------- ka2: Wtil = Wt@Wi_bot -> fragment-packed bf16 hi/lo ----------
__global__ void __launch_bounds__(128) ka2(
    const float* __restrict__ Wt, const float* __restrict__ Wi,
    const float* __restrict__ bi)
{
    int bid = blockIdx.x;
    int m = bid >> 2, dq = bid & 3, j = threadIdx.x;   // j = e
    u32* buf = g_Bpk + (size_t)m * 16384;

    float acc[32];

    if (m == 64) {   // Wi_top: B(e,d) = Wi[d][e]
        #pragma unroll 4
        for (int dd = 0; dd < 32; ++dd)
            acc[dd] = Wi[(dq * 32 + dd) * DD + j];
        if (dq == 0) g_bct[64 * DD + j] = bi[j];
    } else {
        __shared__ float ws[33][129];
        #pragma unroll
        for (int k = 0; k < 32; ++k) {
            int idx = j + k * 128;
            int d = idx >> 7, e = idx & 127;
            ws[d][e] = Wt[(size_t)(m * DD + dq * 32 + d) * DD + e];
        }
        if (dq == 0) ws[32][j] = g_bc[m * DD + j];
        __syncthreads();

        #pragma unroll
        for (int d = 0; d < 32; ++d) acc[d] = 0.f;
        float accb = 0.f;
        for (int e = 0; e < 128; ++e) {
            float wi = Wi[(128 + e) * DD + j];
            #pragma unroll
            for (int d = 0; d < 32; ++d) acc[d] = fmaf(ws[d][e], wi, acc[d]);
            if (dq == 0) accb = fmaf(ws[32][e], wi, accb);
        }
        if (dq == 0) g_bct[m * DD + j] = accb;
    }

    int ntile = j >> 3;
    #pragma unroll
    for (int dd = 0; dd < 32; dd += 2) {
        int d = dq * 32 + dd;
        u16 h0, l0, h1, l1;
        split_bf16(acc[dd], h0, l0);
        split_bf16(acc[dd + 1], h1, l1);
        u32 hw = (u32)h0 | ((u32)h1 << 16);
        u32 lw = (u32)l0 | ((u32)l1 << 16);
        int lane = (j & 7) * 4 + ((d & 7) >> 1);
        int ks = d >> 4;
        int rh = (d >> 3) & 1;
        u32* v = buf + (((ks * 16) + ntile) * 32 + lane) * 4;
        v[rh]     = hw;
        v[2 + rh] = lw;
    }
}

// ---------------- ka3: pack extended W1 [256k x 384n] into frags ----------------
__global__ void __launch_bounds__(128) ka3(
    const float* __restrict__ W1, const float* __restrict__ Wg)
{
    int j = blockIdx.x;        // col 0..383
    int t = threadIdx.x;       // handles k = 2t, 2t+1
    float v0, v1;
    if (j < 256)      { v0 = W1[(2 * t) * 256 + j]; v1 = W1[(2 * t + 1) * 256 + j]; }
    else if (j < 320) {
        int g = j - 256;
        v0 = (t < 64) ? Wg[g * DD + 2 * t]     : 0.f;
        v1 = (t < 64) ? Wg[g * DD + 2 * t + 1] : 0.f;
    } else {
        int g = j - 320;
        v0 = (t < 64) ? g_uT[(2 * t) * MM + g]     : 0.f;
        v1 = (t < 64) ? g_uT[(2 * t + 1) * MM + g] : 0.f;
    }
    u16 h0, l0, h1, l1;
    split_bf16(v0, h0, l0);
    split_bf16(v1, h1, l1);
    u32 hw = (u32)h0 | ((u32)h1 << 16);
    u32 lw = (u32)l0 | ((u32)l1 << 16);
    int lane = (j & 7) * 4 + (t & 3);
    int ks = t >> 3;
    int rh = (t >> 2) & 1;
    int nt = j >> 3;
    u32* v = g_W1pk + (((ks * 48) + nt) * 32 + lane) * 4;
    v[rh]     = hw;
    v[2 + rh] = lw;
}

// ---------------- kb1: extended MMA (h|ta|va), activation, -> g_hta -------------
#define KB1_A    0                       // A hi (32 x 528B) then lo
#define KB1_ALO  16896
#define KB1_B    33792                   // 2 stages x 12288
#define KB1_BIAS 58368                   // 384 x 4
#define SMEM_KB1 59904

__global__ void __launch_bounds__(256, 2) kb1_mma(
    const float* __restrict__ b1, const float* __restrict__ bg)
{
    extern __shared__ __align__(16) char smem[];
    u32 sbase = smem_u32(smem);
    int tid  = threadIdx.x;
    int lane = tid & 31, wid = tid >> 5;
    int wm = wid & 1, wn = wid >> 1;
    int t0 = blockIdx.x * 32;
    int nh = blockIdx.y;                 // n-half: n-tiles nh*24 .. nh*24+23

    {
        #pragma unroll
        for (int r = 0; r < 3; ++r) {
            int idx = tid + r * 256;
            const char* src = (const char*)g_W1pk
                + ((size_t)((0 * 48) + nh * 24 + (idx >> 5)) * 32 + (idx & 31)) * 16;
            cp16(sbase + KB1_B + idx * 16, src);
        }
        asm volatile("cp.async.commit_group;" ::: "memory");
    }
    {
        #pragma unroll
        for (int r = 0; r < 4; ++r) {
            int idx = tid + r * 256;         // 0..1023
            int tok = idx >> 5, c = idx & 31;
            size_t so = (size_t)(t0 + tok) * 512 + c * 16;
            cp16(sbase + KB1_A   + tok * 528 + c * 16, (const char*)g_xchi + so);
            cp16(sbase + KB1_ALO + tok * 528 + c * 16, (const char*)g_xclo + so);
        }
        asm volatile("cp.async.commit_group;" ::: "memory");
    }

    float* bias = (float*)(smem + KB1_BIAS);
    for (int i = tid; i < 384; i += 256) {
        float b;
        if (i < 256)      b = b1[i];
        else if (i < 320) b = bg[i - 256];
        else              b = g_bveff[i - 320];
        bias[i] = b;
    }

    float accY[6][4];
    #pragma unroll
    for (int t = 0; t < 6; ++t)
        #pragma unroll
        for (int q = 0; q < 4; ++q) accY[t][q] = 0.f;

    u32 abyte = (u32)((wm * 16 + (lane & 15)) * 528 + (lane >> 4) * 16);

    for (int ks = 0; ks < 16; ++ks) {
        int s = ks & 1;
        if (ks < 15) {
            u32 dst = sbase + KB1_B + (s ^ 1) * 12288;
            #pragma unroll
            for (int r = 0; r < 3; ++r) {
                int idx = tid + r * 256;
                const char* src = (const char*)g_W1pk
                    + ((size_t)(((ks + 1) * 48) + nh * 24 + (idx >> 5)) * 32 + (idx & 31)) * 16;
                cp16(dst + idx * 16, src);
            }
            asm volatile("cp.async.commit_group;" ::: "memory");
            asm volatile("cp.async.wait_group 1;" ::: "memory");
        } else {
            asm volatile("cp.async.wait_group 0;" ::: "memory");
        }
        __syncthreads();

        u32 ahf[4], alf[4];
        ldsm4(ahf, sbase + KB1_A + abyte + ks * 32);
        ldsm4(alf, sbase + KB1_ALO + abyte + ks * 32);
        u32 bb = sbase + KB1_B + s * 12288;
        #pragma unroll
        for (int t = 0; t < 6; ++t) {
            u32 b4[4];
            lds128(b4, bb + (u32)(((wn * 6 + t) * 32 + lane) * 16));
            mma_bf16(accY[t], ahf, b4);
            mma_bf16(accY[t], ahf, b4 + 2);
            mma_bf16(accY[t], alf, b4);
        }
        __syncthreads();
    }

    int rb = wm * 16 + (lane >> 2);
    #pragma unroll
    for (int t = 0; t < 6; ++t) {
        int col = (nh * 24 + wn * 6 + t) * 8 + 2 * (lane & 3);
        float b0 = bias[col], b1v = bias[col + 1];
        float v00 = accY[t][0] + b0, v01 = accY[t][1] + b1v;
        float v10 = accY[t][2] + b0, v11 = accY[t][3] + b1v;
        if (col < 256) {
            v00 = 0.5f * v00 * (1.0f + erff(v00 * 0.70710678118654752f));
            v01 = 0.5f * v01 * (1.0f + erff(v01 * 0.70710678118654752f));
            v10 = 0.5f * v10 * (1.0f + erff(v10 * 0.70710678118654752f));
            v11 = 0.5f * v11 * (1.0f + erff(v11 * 0.70710678118654752f));
        } else {
            v00 = 1.0f / (1.0f + expf(-v00));
            v01 = 1.0f / (1.0f + expf(-v01));
            v10 = 1.0f / (1.0f + expf(-v10));
            v11 = 1.0f / (1.0f + expf(-v11));
        }
        *(float2*)&g_hta[(size_t)(t0 + rb) * 384 + col]     = make_float2(v00, v01);
        *(float2*)&g_hta[(size_t)(t0 + rb + 8) * 384 + col] = make_float2(v10, v11);
    }
}

// ---------------- kb2: W2+O smem-staged / softmax / gates / c / victory ---------
#define KB2_W2   0                       // 64 KB
#define KB2_O    65536                   // 16 KB
#define KB2_H    81920                   // 16 x 260 fp32 = 16640
#define KB2_LS   98560                   // 16 x 68 fp32 = 4352
#define KB2_VS   102912                  // 4352
#define SMEM_KB2 107264

__global__ void __launch_bounds__(256) kb2_sel(
    const float* __restrict__ W2, const float* __restrict__ b2,
    const float* __restrict__ O,  float* __restrict__ out)
{
    extern __shared__ __align__(16) char smem[];
    u32 sbase = smem_u32(smem);
    float* w2s = (float*)(smem + KB2_W2);
    float* os  = (float*)(smem + KB2_O);
    float* hsm = (float*)(smem + KB2_H);
    float* ls  = (float*)(smem + KB2_LS);
    float* vs  = (float*)(smem + KB2_VS);

    int t0 = blockIdx.x * 16;
    int tid = threadIdx.x;

    #pragma unroll
    for (int r = 0; r < 16; ++r) {
        int idx = tid + r * 256;
        cp16(sbase + KB2_W2 + idx * 16, (const char*)W2 + (size_t)idx * 16);
    }
    #pragma unroll
    for (int r = 0; r < 4; ++r) {
        int idx = tid + r * 256;
        cp16(sbase + KB2_O + idx * 16, (const char*)O + (size_t)idx * 16);
    }
    asm volatile("cp.async.commit_group;" ::: "memory");

    #pragma unroll
    for (int r = 0; r < 4; ++r) {
        int idx = tid + r * 256;
        int tok = idx >> 6, cq = idx & 63;
        *(float4*)&hsm[tok * 260 + cq * 4] =
            *(const float4*)&g_hta[(size_t)(t0 + tok) * 384 + cq * 4];
    }
    asm volatile("cp.async.wait_group 0;" ::: "memory");
    __syncthreads();

    int n  = tid & 63;
    int tq = tid >> 6;
    int tb = tq * 4;

    {
        float acc[4];
        float bn = b2[n];
        #pragma unroll
        for (int q = 0; q < 4; ++q) acc[q] = bn;
        for (int j = 0; j < 256; j += 4) {
            float w0 = w2s[j * 64 + n];
            float w1 = w2s[(j + 1) * 64 + n];
            float w2v = w2s[(j + 2) * 64 + n];
            float w3 = w2s[(j + 3) * 64 + n];
            #pragma unroll
            for (int q = 0; q < 4; ++q) {
                float4 h4 = *(const float4*)&hsm[(tb + q) * 260 + j];
                acc[q] = fmaf(h4.x, w0, acc[q]);
                acc[q] = fmaf(h4.y, w1, acc[q]);
                acc[q] = fmaf(h4.z, w2v, acc[q]);
                acc[q] = fmaf(h4.w, w3, acc[q]);
            }
        }
        #pragma unroll
        for (int q = 0; q < 4; ++q) ls[(tb + q) * 68 + n] = acc[q];
    }
    __syncthreads();

    if (tid < 16) {
        float* row = ls + tid * 68;
        float mx = -1e30f;
        #pragma unroll
        for (int k = 0; k < 64; ++k) mx = fmaxf(mx, row[k]);
        float s = 0.f;
        #pragma unroll
        for (int k = 0; k < 64; ++k) { float e = expf(row[k] - mx); row[k] = e; s += e; }
        float inv = 1.0f / s;
        #pragma unroll
        for (int k = 0; k < 64; ++k) row[k] *= inv;
    }
    __syncthreads();

    {
        float gl[4];
        #pragma unroll
        for (int q = 0; q < 4; ++q) gl[q] = 0.f;
        for (int mm = 0; mm < 64; ++mm) {
            float o = os[mm * 64 + n];
            #pragma unroll
            for (int q = 0; q < 4; ++q) gl[q] = fmaf(ls[(tb + q) * 68 + mm], o, gl[q]);
        }
        #pragma unroll
        for (int q = 0; q < 4; ++q) {
            int tok = tb + q;
            float sc     = ls[tok * 68 + n];
            float timing = g_hta[(size_t)(t0 + tok) * 384 + 256 + n];
            float vic    = g_hta[(size_t)(t0 + tok) * 384 + 320 + n];
            float gate   = 1.0f + tanhf(gl[q]);
            g_cbuf[(size_t)(t0 + tok) * MM + n] = timing * gate * sc;
            vs[tok * 68 + n] = vic * sc;
        }
    }
    __syncthreads();

    if (tid < 16) {
        float s = 0.f;
        #pragma unroll
        for (int k = 0; k < 64; ++k) s += vs[tid * 68 + k];
        out[(size_t)T_TOK * DD + t0 + tid] = s;
    }
}

// ---------------- kc: 128-token tile, 2 row-frags/warp share B fragments --------
// grid (64, GROUPS), 512 threads = 16 warps: wm=wid&3 (32 tok), wn=wid>>2 (32 e).
#define APAD     136
#define OFF_W    0                        // 2 stages x 64KB
#define OFF_AHI  131072                   // 128 x 272B = 34816
#define OFF_ALO  165888
#define OFF_CS   200704                   // 13 x 128 x 4 = 6656
#define OFF_BCT  207360                   // 6656
#define SMEM_KC  214016

__global__ void __launch_bounds__(512, 1) kc_mma()
{
    extern __shared__ __align__(16) char smem[];
    u32 sbase = smem_u32(smem);
    float* cs_s  = (float*)(smem + OFF_CS);
    float* bct_s = (float*)(smem + OFF_BCT);

    int tid  = threadIdx.x;
    int lane = tid & 31, wid = tid >> 5;
    int wm = wid & 3, wn = wid >> 2;
    int t0 = blockIdx.x * 128;
    int m0 = blockIdx.y * NMG;

    // group 0: W[m0] stage 0 + A hi/lo (x cols) from precomputed split
    {
        const char* src = (const char*)g_Bpk + (size_t)m0 * 65536;
        #pragma unroll
        for (int r = 0; r < 8; ++r) {
            int idx = tid + r * 512;
            cp16(sbase + OFF_W + idx * 16, src + (size_t)idx * 16);
        }
        #pragma unroll
        for (int r = 0; r < 4; ++r) {
            int idx = tid + r * 512;          // 0..2047
            int tok = idx >> 4, c = idx & 15;
            size_t so = (size_t)(t0 + tok) * 512 + c * 16;   // first 128 cols = x
            cp16(sbase + OFF_AHI + tok * 272 + c * 16, (const char*)g_xchi + so);
            cp16(sbase + OFF_ALO + tok * 272 + c * 16, (const char*)g_xclo + so);
        }
        asm volatile("cp.async.commit_group;" ::: "memory");
    }

    for (int i = tid; i < NMG * 128; i += 512) {
        int mi = i >> 7, r = i & 127;
        int gm = m0 + mi;
        cs_s[i] = (gm == 64) ? 1.0f : g_cbuf[(size_t)(t0 + r) * MM + gm];
    }
    for (int i = tid; i < NMG * 128; i += 512) {
        int mi = i >> 7, r = i & 127;
        bct_s[i] = g_bct[(m0 + mi) * DD + r];
    }

    asm volatile("cp.async.wait_group 0;" ::: "memory");
    __syncthreads();

    // A fragment byte offsets for the 2 row-frags (re-read per ks; no hoist)
    u32 a0off = (u32)((wm * 32 + (lane & 15)) * (APAD * 2) + (lane >> 4) * 16);
    u32 a1off = a0off + 16 * (APAD * 2);

    float accF[2][4][4];
    #pragma unroll
    for (int rf = 0; rf < 2; ++rf)
        #pragma unroll
        for (int nt = 0; nt < 4; ++nt)
            #pragma unroll
            for (int j = 0; j < 4; ++j) accF[rf][nt][j] = 0.f;

    int rb = wm * 32 + (lane >> 2);        // row within 128-token tile (rf adds 16)
    int cb = wn * 32 + 2 * (lane & 3);

    for (int mi = 0; mi < NMG; ++mi) {
        int s = mi & 1;
        if (mi + 1 < NMG) {
            const char* src = (const char*)g_Bpk + (size_t)(m0 + mi + 1) * 65536;
            u32 dst = sbase + OFF_W + (s ^ 1) * 65536;
            #pragma unroll
            for (int r = 0; r < 8; ++r) {
                int idx = tid + r * 512;
                cp16(dst + idx * 16, src + (size_t)idx * 16);
            }
            asm volatile("cp.async.commit_group;" ::: "memory");
            asm volatile("cp.async.wait_group 1;" ::: "memory");
        } else {
            asm volatile("cp.async.wait_group 0;" ::: "memory");
        }
        __syncthreads();

        float accY[2][4][4];
        #pragma unroll
        for (int rf = 0; rf < 2; ++rf)
            #pragma unroll
            for (int nt = 0; nt < 4; ++nt)
                #pragma unroll
                for (int j = 0; j < 4; ++j) accY[rf][nt][j] = 0.f;

        u32 wbase = sbase + OFF_W + s * 65536;
        #pragma unroll
        for (int ks = 0; ks < 8; ++ks) {
            u32 Ah0[4], Al0[4], Ah1[4], Al1[4];
            ldsm4(Ah0, sbase + OFF_AHI + a0off + ks * 32);
            ldsm4(Al0, sbase + OFF_ALO + a0off + ks * 32);
            ldsm4(Ah1, sbase + OFF_AHI + a1off + ks * 32);
            ldsm4(Al1, sbase + OFF_ALO + a1off + ks * 32);
            u32 b4[4][4];
            #pragma unroll
            for (int nt = 0; nt < 4; ++nt)
                lds128(b4[nt], wbase + (((ks * 16) + wn * 4 + nt) * 32 + lane) * 16);
            // term-major over nt for ILP; B frags reused across both row frags
            #pragma unroll
            for (int nt = 0; nt < 4; ++nt) mma_bf16(accY[0][nt], Ah0, b4[nt]);
            #pragma unroll
            for (int nt = 0; nt < 4; ++nt) mma_bf16(accY[1][nt], Ah1, b4[nt]);
            #pragma unroll
            for (int nt = 0; nt < 4; ++nt) mma_bf16(accY[0][nt], Ah0, b4[nt] + 2);
            #pragma unroll
            for (int nt = 0; nt < 4; ++nt) mma_bf16(accY[1][nt], Ah1, b4[nt] + 2);
            #pragma unroll
            for (int nt = 0; nt < 4; ++nt) mma_bf16(accY[0][nt], Al0, b4[nt]);
            #pragma unroll
            for (int nt = 0; nt < 4; ++nt) mma_bf16(accY[1][nt], Al1, b4[nt]);
        }

        #pragma unroll
        for (int rf = 0; rf < 2; ++rf) {
            float c0 = cs_s[mi * 128 + rb + rf * 16];
            float c1 = cs_s[mi * 128 + rb + rf * 16 + 8];
            #pragma unroll
            for (int nt = 0; nt < 4; ++nt) {
                float2 bb = *(const float2*)&bct_s[mi * 128 + cb + nt * 8];
                accF[rf][nt][0] = fmaf(c0, accY[rf][nt][0] + bb.x, accF[rf][nt][0]);
                accF[rf][nt][1] = fmaf(c0, accY[rf][nt][1] + bb.y, accF[rf][nt][1]);
                accF[rf][nt][2] = fmaf(c1, accY[rf][nt][2] + bb.x, accF[rf][nt][2]);
                accF[rf][nt][3] = fmaf(c1, accY[rf][nt][3] + bb.y, accF[rf][nt][3]);
            }
        }
        __syncthreads();
    }

    float* part = g_part + (size_t)blockIdx.y * T_TOK * DD;
    #pragma unroll
    for (int rf = 0; rf < 2; ++rf) {
        int row = t0 + rb + rf * 16;
        #pragma unroll
        for (int nt = 0; nt < 4; ++nt) {
            int col = cb + nt * 8;
            *(float2*)&part[(size_t)row * DD + col]       = make_float2(accF[rf][nt][0], accF[rf][nt][1]);
            *(float2*)&part[(size_t)(row + 8) * DD + col] = make_float2(accF[rf][nt][2], accF[rf][nt][3]);
        }
    }
}

// ---------------- kd: combine GROUPS partials ----------------------------------
__global__ void __launch_bounds__(256) kd_combine(float* __restrict__ out)
{
    int i = blockIdx.x * 256 + threadIdx.x;
    float4 r = make_float4(0.f, 0.f, 0.f, 0.f);
    #pragma unroll
    for (int g = 0; g < GROUPS; ++g) {
        float4 a = ((const float4*)(g_part + (size_t)g * T_TOK * DD))[i];
        r.x += a.x; r.y += a.y; r.z += a.z; r.w += a.w;
    }
    ((float4*)out)[i] = r;
}

// ---------------- launch ------------------------------------------------------
extern "C" void kernel_launch(void* const* d_in, const int* in_sizes, int n_in,
                              void* d_out, int out_size)
{
    const float* x    = (const float*)d_in[0];
    const float* ctx  = (const float*)d_in[1];
    const float* Wt   = (const float*)d_in[2];
    const float* bt   = (const float*)d_in[3];
    const float* chr  = (const float*)d_in[4];
    const float* Wg   = (const float*)d_in[5];
    const float* bg   = (const float*)d_in[6];
    const float* Wv   = (const float*)d_in[7];
    const float* bv   = (const float*)d_in[8];
    const float* O    = (const float*)d_in[9];
    const float* W1   = (const float*)d_in[10];
    const float* b1   = (const float*)d_in[11];
    const float* W2   = (const float*)d_in[12];
    const float* b2   = (const float*)d_in[13];
    const float* Wi   = (const float*)d_in[14];
    const float* bi   = (const float*)d_in[15];
    float* out = (float*)d_out;

    cudaFuncSetAttribute(kc_mma, cudaFuncAttributeMaxDynamicSharedMemorySize, SMEM_KC);
    cudaFuncSetAttribute(kb1_mma, cudaFuncAttributeMaxDynamicSharedMemorySize, SMEM_KB1);
    cudaFuncSetAttribute(kb2_sel, cudaFuncAttributeMaxDynamicSharedMemorySize, SMEM_KB2);

    kx_split<<<T_TOK * 64 / 256, 256>>>(x, ctx);
    ka1<<<64, 128>>>(Wt, bt, chr, Wv, bv);
    ka2<<<260, 128>>>(Wt, Wi, bi);
    ka3<<<384, 128>>>(W1, Wg);
    kb1_mma<<<dim3(T_TOK / 32, 2), 256, SMEM_KB1>>>(b1, bg);
    kb2_sel<<<T_TOK / 16, 256, SMEM_KB2>>>(W2, b2, O, out);
    kc_mma<<<dim3(T_TOK / 128, GROUPS), 512, SMEM_KC>>>();
    kd_combine<<<(T_TOK * DD / 4) / 256, 256>>>(out);
}

// round 16
// speedup vs baseline: 1.1393x; 1.1393x over previous
#include <cuda_runtime.h>
#include <cuda_bf16.h>
#include <math.h>

#define T_TOK 8192
#define DD    128
#define MM    64
#define GROUPS 5
#define NMG   13          // mechanisms per group (5*13 = 65)

typedef unsigned long long ull;
typedef unsigned int u32;
typedef unsigned short u16;

// ---------------- scratch ----------------------------------------------------
__device__ float g_cbuf[T_TOK * MM];        // c[t][m]
__device__ float g_uT[DD * MM];             // [d][m]
__device__ float g_bveff[MM];
__device__ float g_bc[MM * DD];             // bt + char
__device__ float g_bct[65 * DD];            // bctil[m] ; m=64 -> bi
__device__ u32   g_Bpk[65 * 16384];         // kc W frag-packed
__device__ u32   g_W1pk[16 * 48 * 32 * 4];  // kb extended-W frag-packed (384 cols)
__device__ float g_hta[(size_t)T_TOK * 384];// kb1 output: gelu(h) | timing | victory
__device__ float g_part[GROUPS * T_TOK * DD];

// ---------------- helpers ------------------------------------------------------
__device__ __forceinline__ u32 smem_u32(const void* p) {
    u32 a;
    asm("{ .reg .u64 t; cvta.to.shared.u64 t, %1; cvt.u32.u64 %0, t; }" : "=r"(a) : "l"(p));
    return a;
}
__device__ __forceinline__ void mma_bf16(float* c, const u32* a, const u32* b) {
    asm volatile("mma.sync.aligned.m16n8k16.row.col.f32.bf16.bf16.f32 "
        "{%0,%1,%2,%3}, {%4,%5,%6,%7}, {%8,%9}, {%0,%1,%2,%3};"
        : "+f"(c[0]), "+f"(c[1]), "+f"(c[2]), "+f"(c[3])
        : "r"(a[0]), "r"(a[1]), "r"(a[2]), "r"(a[3]), "r"(b[0]), "r"(b[1]));
}
__device__ __forceinline__ void ldsm4(u32* r, u32 addr) {
    asm volatile("ldmatrix.sync.aligned.m8n8.x4.shared.b16 {%0,%1,%2,%3}, [%4];"
        : "=r"(r[0]), "=r"(r[1]), "=r"(r[2]), "=r"(r[3]) : "r"(addr));
}
__device__ __forceinline__ void lds128(u32* r, u32 addr) {
    asm volatile("ld.shared.v4.u32 {%0,%1,%2,%3}, [%4];"
        : "=r"(r[0]), "=r"(r[1]), "=r"(r[2]), "=r"(r[3]) : "r"(addr));
}
__device__ __forceinline__ void cp16(u32 dst, const void* src) {
    asm volatile("cp.async.cg.shared.global [%0], [%1], 16;" :: "r"(dst), "l"(src) : "memory");
}
__device__ __forceinline__ void split_bf16(float v, u16& h, u16& l) {
    __nv_bfloat16 hb = __float2bfloat16_rn(v);
    float r = v - __bfloat162float(hb);
    h = __bfloat16_as_ushort(hb);
    l = __bfloat16_as_ushort(__float2bfloat16_rn(r));
}

// ---------------- ka1: bc, bveff, uT --------------------------------------------
__global__ void __launch_bounds__(128) ka1(
    const float* __restrict__ Wt, const float* __restrict__ bt,
    const float* __restrict__ chr,
    const float* __restrict__ Wv, const float* __restrict__ bv)
{
    int m = blockIdx.x, tid = threadIdx.x;
    int lane = tid & 31, warp = tid >> 5;
    __shared__ float red[4];

    float wv  = Wv[m * DD + tid];
    float bcv = bt[m * DD + tid] + chr[m * DD + tid];
    g_bc[m * DD + tid]  = bcv;

    float v = bcv * wv;
    #pragma unroll
    for (int o = 16; o > 0; o >>= 1) v += __shfl_down_sync(0xffffffffu, v, o);
    if (lane == 0) red[warp] = v;
    __syncthreads();
    if (tid == 0) g_bveff[m] = bv[m] + red[0] + red[1] + red[2] + red[3];

    const float4* W4 = (const float4*)Wt + (size_t)m * 4096;
    float4 wv4 = ((const float4*)(Wv + m * DD))[lane];
    for (int r = warp; r < DD; r += 8) {
        float4 w0 = W4[r * 32 + lane];
        float4 w1 = W4[(r + 4) * 32 + lane];
        float a0 = w0.x * wv4.x + w0.y * wv4.y + w0.z * wv4.z + w0.w * wv4.w;
        float a1 = w1.x * wv4.x + w1.y * wv4.y + w1.z * wv4.z + w1.w * wv4.w;
        #pragma unroll
        for (int o = 16; o > 0; o >>= 1) {
            a0 += __shfl_down_sync(0xffffffffu, a0, o);
            a1 += __shfl_down_sync(0xffffffffu, a1, o);
        }
        if (lane == 0) {
            g_uT[r * MM + m]       = a0;
            g_uT[(r + 4) * MM + m] = a1;
        }
    }
}

// ---------------- ka2: Wtil = Wt@Wi_bot -> fragment-packed bf16 hi/lo ----------
// grid 520: m = bid>>3, dq = bid&7 (16 d-rows per block for occupancy)
__global__ void __launch_bounds__(128) ka2(
    const float* __restrict__ Wt, const float* __restrict__ Wi,
    const float* __restrict__ bi)
{
    int bid = blockIdx.x;
    int m = bid >> 3, dq = bid & 7, j = threadIdx.x;   // j = e
    u32* buf = g_Bpk + (size_t)m * 16384;

    float acc[16];

    if (m == 64) {   // Wi_top: B(e,d) = Wi[d][e]
        #pragma unroll 4
        for (int dd = 0; dd < 16; ++dd)
            acc[dd] = Wi[(dq * 16 + dd) * DD + j];
        if (dq == 0) g_bct[64 * DD + j] = bi[j];
    } else {
        __shared__ float ws[17][129];
        #pragma unroll
        for (int k = 0; k < 16; ++k) {
            int idx = j + k * 128;
            int d = idx >> 7, e = idx & 127;
            ws[d][e] = Wt[(size_t)(m * DD + dq * 16 + d) * DD + e];
        }
        if (dq == 0) ws[16][j] = g_bc[m * DD + j];
        __syncthreads();

        #pragma unroll
        for (int d = 0; d < 16; ++d) acc[d] = 0.f;
        float accb = 0.f;
        for (int e = 0; e < 128; ++e) {
            float wi = Wi[(128 + e) * DD + j];
            #pragma unroll
            for (int d = 0; d < 16; ++d) acc[d] = fmaf(ws[d][e], wi, acc[d]);
            if (dq == 0) accb = fmaf(ws[16][e], wi, accb);
        }
        if (dq == 0) g_bct[m * DD + j] = accb;
    }

    int ntile = j >> 3;
    #pragma unroll
    for (int dd = 0; dd < 16; dd += 2) {
        int d = dq * 16 + dd;
        u16 h0, l0, h1, l1;
        split_bf16(acc[dd], h0, l0);
        split_bf16(acc[dd + 1], h1, l1);
        u32 hw = (u32)h0 | ((u32)h1 << 16);
        u32 lw = (u32)l0 | ((u32)l1 << 16);
        int lane = (j & 7) * 4 + ((d & 7) >> 1);
        int ks = d >> 4;
        int rh = (d >> 3) & 1;
        u32* v = buf + (((ks * 16) + ntile) * 32 + lane) * 4;
        v[rh]     = hw;
        v[2 + rh] = lw;
    }
}

// ---------------- ka3: pack extended W1 [256k x 384n] into frags ----------------
__global__ void __launch_bounds__(128) ka3(
    const float* __restrict__ W1, const float* __restrict__ Wg)
{
    int j = blockIdx.x;        // col 0..383
    int t = threadIdx.x;       // handles k = 2t, 2t+1
    float v0, v1;
    if (j < 256)      { v0 = W1[(2 * t) * 256 + j]; v1 = W1[(2 * t + 1) * 256 + j]; }
    else if (j < 320) {
        int g = j - 256;
        v0 = (t < 64) ? Wg[g * DD + 2 * t]     : 0.f;
        v1 = (t < 64) ? Wg[g * DD + 2 * t + 1] : 0.f;
    } else {
        int g = j - 320;
        v0 = (t < 64) ? g_uT[(2 * t) * MM + g]     : 0.f;
        v1 = (t < 64) ? g_uT[(2 * t + 1) * MM + g] : 0.f;
    }
    u16 h0, l0, h1, l1;
    split_bf16(v0, h0, l0);
    split_bf16(v1, h1, l1);
    u32 hw = (u32)h0 | ((u32)h1 << 16);
    u32 lw = (u32)l0 | ((u32)l1 << 16);
    int lane = (j & 7) * 4 + (t & 3);
    int ks = t >> 3;
    int rh = (t >> 2) & 1;
    int nt = j >> 3;
    u32* v = g_W1pk + (((ks * 48) + nt) * 32 + lane) * 4;
    v[rh]     = hw;
    v[2 + rh] = lw;
}

// ---------------- kb1: extended MMA (h|ta|va), activation, -> g_hta -------------
#define KB1_A    0                       // A hi (32 x 528B) then lo
#define KB1_ALO  16896
#define KB1_B    33792                   // 2 stages x 12288
#define KB1_BIAS 58368                   // 384 x 4
#define SMEM_KB1 59904

__global__ void __launch_bounds__(256, 2) kb1_mma(
    const float* __restrict__ x, const float* __restrict__ ctx,
    const float* __restrict__ b1, const float* __restrict__ bg)
{
    extern __shared__ __align__(16) char smem[];
    u32 sbase = smem_u32(smem);
    int tid  = threadIdx.x;
    int lane = tid & 31, wid = tid >> 5;
    int wm = wid & 1, wn = wid >> 1;
    int t0 = blockIdx.x * 32;
    int nh = blockIdx.y;                 // n-half: n-tiles nh*24 .. nh*24+23

    {
        #pragma unroll
        for (int r = 0; r < 3; ++r) {
            int idx = tid + r * 256;
            const char* src = (const char*)g_W1pk
                + ((size_t)((0 * 48) + nh * 24 + (idx >> 5)) * 32 + (idx & 31)) * 16;
            cp16(sbase + KB1_B + idx * 16, src);
        }
        asm volatile("cp.async.commit_group;" ::: "memory");
    }

    // A = concat(x,ctx) split bf16 hi/lo (row stride 264 u16 = 528B)
    {
        u16* ah = (u16*)(smem + KB1_A);
        u16* al = (u16*)(smem + KB1_ALO);
        #pragma unroll
        for (int r = 0; r < 8; ++r) {
            int idx = tid + r * 256;
            int tok = idx >> 6, cq = idx & 63;
            float4 v = (cq < 32) ? ((const float4*)(x   + (size_t)(t0 + tok) * DD))[cq]
                                 : ((const float4*)(ctx + (size_t)(t0 + tok) * DD))[cq - 32];
            u16 h[4], l[4];
            split_bf16(v.x, h[0], l[0]); split_bf16(v.y, h[1], l[1]);
            split_bf16(v.z, h[2], l[2]); split_bf16(v.w, h[3], l[3]);
            int o = tok * 264 + cq * 4;
            *(uint2*)&ah[o] = make_uint2((u32)h[0] | ((u32)h[1] << 16), (u32)h[2] | ((u32)h[3] << 16));
            *(uint2*)&al[o] = make_uint2((u32)l[0] | ((u32)l[1] << 16), (u32)l[2] | ((u32)l[3] << 16));
        }
    }

    float* bias = (float*)(smem + KB1_BIAS);
    for (int i = tid; i < 384; i += 256) {
        float b;
        if (i < 256)      b = b1[i];
        else if (i < 320) b = bg[i - 256];
        else              b = g_bveff[i - 320];
        bias[i] = b;
    }
    __syncthreads();

    float accY[6][4];
    #pragma unroll
    for (int t = 0; t < 6; ++t)
        #pragma unroll
        for (int q = 0; q < 4; ++q) accY[t][q] = 0.f;

    u32 abyte = (u32)((wm * 16 + (lane & 15)) * 528 + (lane >> 4) * 16);

    for (int ks = 0; ks < 16; ++ks) {
        int s = ks & 1;
        if (ks < 15) {
            u32 dst = sbase + KB1_B + (s ^ 1) * 12288;
            #pragma unroll
            for (int r = 0; r < 3; ++r) {
                int idx = tid + r * 256;
                const char* src = (const char*)g_W1pk
                    + ((size_t)(((ks + 1) * 48) + nh * 24 + (idx >> 5)) * 32 + (idx & 31)) * 16;
                cp16(dst + idx * 16, src);
            }
            asm volatile("cp.async.commit_group;" ::: "memory");
            asm volatile("cp.async.wait_group 1;" ::: "memory");
        } else {
            asm volatile("cp.async.wait_group 0;" ::: "memory");
        }
        __syncthreads();

        u32 ahf[4], alf[4];
        ldsm4(ahf, sbase + KB1_A + abyte + ks * 32);
        ldsm4(alf, sbase + KB1_ALO + abyte + ks * 32);
        u32 bb = sbase + KB1_B + s * 12288;
        #pragma unroll
        for (int t = 0; t < 6; ++t) {
            u32 b4[4];
            lds128(b4, bb + (u32)(((wn * 6 + t) * 32 + lane) * 16));
            mma_bf16(accY[t], ahf, b4);
            mma_bf16(accY[t], ahf, b4 + 2);
            mma_bf16(accY[t], alf, b4);
        }
        __syncthreads();
    }

    int rb = wm * 16 + (lane >> 2);
    #pragma unroll
    for (int t = 0; t < 6; ++t) {
        int col = (nh * 24 + wn * 6 + t) * 8 + 2 * (lane & 3);
        float b0 = bias[col], b1v = bias[col + 1];
        float v00 = accY[t][0] + b0, v01 = accY[t][1] + b1v;
        float v10 = accY[t][2] + b0, v11 = accY[t][3] + b1v;
        if (col < 256) {
            v00 = 0.5f * v00 * (1.0f + erff(v00 * 0.70710678118654752f));
            v01 = 0.5f * v01 * (1.0f + erff(v01 * 0.70710678118654752f));
            v10 = 0.5f * v10 * (1.0f + erff(v10 * 0.70710678118654752f));
            v11 = 0.5f * v11 * (1.0f + erff(v11 * 0.70710678118654752f));
        } else {
            v00 = 1.0f / (1.0f + expf(-v00));
            v01 = 1.0f / (1.0f + expf(-v01));
            v10 = 1.0f / (1.0f + expf(-v10));
            v11 = 1.0f / (1.0f + expf(-v11));
        }
        *(float2*)&g_hta[(size_t)(t0 + rb) * 384 + col]     = make_float2(v00, v01);
        *(float2*)&g_hta[(size_t)(t0 + rb + 8) * 384 + col] = make_float2(v10, v11);
    }
}

// ---------------- kb2: 64-token CTAs; W2+O staged once; softmax over 64 threads -
#define KB2_W2   0                       // 64 KB
#define KB2_O    65536                   // 16 KB
#define KB2_H    81920                   // 64 x 260 fp32 = 66560
#define KB2_LS   148480                  // 64 x 68 fp32 = 17408
#define KB2_VS   165888                  // 17408
#define SMEM_KB2 183296

__global__ void __launch_bounds__(512) kb2_sel(
    const float* __restrict__ W2, const float* __restrict__ b2,
    const float* __restrict__ O,  float* __restrict__ out)
{
    extern __shared__ __align__(16) char smem[];
    u32 sbase = smem_u32(smem);
    float* w2s = (float*)(smem + KB2_W2);
    float* os  = (float*)(smem + KB2_O);
    float* hsm = (float*)(smem + KB2_H);
    float* ls  = (float*)(smem + KB2_LS);
    float* vs  = (float*)(smem + KB2_VS);

    int t0 = blockIdx.x * 64;
    int tid = threadIdx.x;

    // stage W2 (64 KB) + O (16 KB) + h tile (64x256 fp32) via cp.async
    #pragma unroll
    for (int r = 0; r < 8; ++r) {
        int idx = tid + r * 512;
        cp16(sbase + KB2_W2 + idx * 16, (const char*)W2 + (size_t)idx * 16);
    }
    #pragma unroll
    for (int r = 0; r < 2; ++r) {
        int idx = tid + r * 512;
        cp16(sbase + KB2_O + idx * 16, (const char*)O + (size_t)idx * 16);
    }
    #pragma unroll
    for (int r = 0; r < 8; ++r) {
        int idx = tid + r * 512;            // 0..4095
        int tok = idx >> 6, cq = idx & 63;
        cp16(sbase + KB2_H + tok * 1040 + cq * 16,
             (const char*)(g_hta + (size_t)(t0 + tok) * 384 + cq * 4));
    }
    asm volatile("cp.async.commit_group;" ::: "memory");
    asm volatile("cp.async.wait_group 0;" ::: "memory");
    __syncthreads();

    int n  = tid & 63;
    int tg = tid >> 6;          // 8 token groups x 8 tokens

    // logits = h @ W2 + b2 (all smem)
    {
        float acc[8];
        float bn = b2[n];
        #pragma unroll
        for (int q = 0; q < 8; ++q) acc[q] = bn;
        for (int j = 0; j < 256; j += 4) {
            float w0 = w2s[j * 64 + n];
            float w1 = w2s[(j + 1) * 64 + n];
            float w2v = w2s[(j + 2) * 64 + n];
            float w3 = w2s[(j + 3) * 64 + n];
            #pragma unroll
            for (int q = 0; q < 8; ++q) {
                float4 h4 = *(const float4*)&hsm[(tg * 8 + q) * 260 + j];
                acc[q] = fmaf(h4.x, w0, acc[q]);
                acc[q] = fmaf(h4.y, w1, acc[q]);
                acc[q] = fmaf(h4.z, w2v, acc[q]);
                acc[q] = fmaf(h4.w, w3, acc[q]);
            }
        }
        #pragma unroll
        for (int q = 0; q < 8; ++q) ls[(tg * 8 + q) * 68 + n] = acc[q];
    }
    __syncthreads();

    // softmax per token (64 threads)
    if (tid < 64) {
        float* row = ls + tid * 68;
        float mx = -1e30f;
        #pragma unroll
        for (int k = 0; k < 64; ++k) mx = fmaxf(mx, row[k]);
        float s = 0.f;
        #pragma unroll
        for (int k = 0; k < 64; ++k) { float e = expf(row[k] - mx); row[k] = e; s += e; }
        float inv = 1.0f / s;
        #pragma unroll
        for (int k = 0; k < 64; ++k) row[k] *= inv;
    }
    __syncthreads();

    // gates / c / victory
    {
        float gl[8];
        #pragma unroll
        for (int q = 0; q < 8; ++q) gl[q] = 0.f;
        for (int mm = 0; mm < 64; ++mm) {
            float o = os[mm * 64 + n];
            #pragma unroll
            for (int q = 0; q < 8; ++q)
                gl[q] = fmaf(ls[(tg * 8 + q) * 68 + mm], o, gl[q]);
        }
        #pragma unroll
        for (int q = 0; q < 8; ++q) {
            int tok = tg * 8 + q;
            float sc     = ls[tok * 68 + n];
            float timing = hsm[tok * 260 + 256 + n - ((n < 4) ? 0 : 0)];   // placeholder replaced below
            (void)timing;
        }
        // timing/victory live in g_hta cols 256..383 (not staged in hsm's 256-col tile)
        #pragma unroll
        for (int q = 0; q < 8; ++q) {
            int tok = tg * 8 + q;
            float sc     = ls[tok * 68 + n];
            float timing = g_hta[(size_t)(t0 + tok) * 384 + 256 + n];
            float vic    = g_hta[(size_t)(t0 + tok) * 384 + 320 + n];
            float gate   = 1.0f + tanhf(gl[q]);
            g_cbuf[(size_t)(t0 + tok) * MM + n] = timing * gate * sc;
            vs[tok * 68 + n] = vic * sc;
        }
    }
    __syncthreads();

    if (tid < 64) {
        float s = 0.f;
        #pragma unroll
        for (int k = 0; k < 64; ++k) s += vs[tid * 68 + k];
        out[(size_t)T_TOK * DD + t0 + tid] = s;
    }
}

// ---------------- kc: mma.sync bf16-split fused GEMM (R11/R13 proven config) ----
#define APAD     136
#define OFF_W    0
#define OFF_AHI  131072
#define OFF_ALO  148480
#define OFF_CS   165888
#define OFF_BCT  169216
#define SMEM_KC  175872

__global__ void __launch_bounds__(512, 1) kc_mma(const float* __restrict__ x)
{
    extern __shared__ __align__(16) char smem[];
    u32 sbase = smem_u32(smem);
    float* cs_s  = (float*)(smem + OFF_CS);
    float* bct_s = (float*)(smem + OFF_BCT);

    int tid  = threadIdx.x;
    int lane = tid & 31, wid = tid >> 5;
    int wm = wid & 3, wn = wid >> 2;
    int t0 = blockIdx.x * 64;
    int m0 = blockIdx.y * NMG;

    for (int i = tid; i < NMG * 64; i += 512) {
        int mi = i >> 6, r = i & 63;
        int gm = m0 + mi;
        cs_s[i] = (gm == 64) ? 1.0f : g_cbuf[(size_t)(t0 + r) * MM + gm];
    }
    for (int i = tid; i < NMG * 128; i += 512) {
        int mi = i >> 7, r = i & 127;
        bct_s[i] = g_bct[(m0 + mi) * DD + r];
    }

    {
        const char* src = (const char*)g_Bpk + (size_t)m0 * 65536;
        #pragma unroll
        for (int r = 0; r < 8; ++r) {
            int idx = tid + r * 512;
            cp16(sbase + OFF_W + idx * 16, src + (size_t)idx * 16);
        }
        asm volatile("cp.async.commit_group;" ::: "memory");
    }

    {
        u16* ah = (u16*)(smem + OFF_AHI);
        u16* al = (u16*)(smem + OFF_ALO);
        #pragma unroll
        for (int r = 0; r < 4; ++r) {
            int idx = tid + r * 512;
            int tok = idx >> 5, dq = idx & 31;
            float4 v = ((const float4*)(x + (size_t)(t0 + tok) * DD))[dq];
            u16 h[4], l[4];
            split_bf16(v.x, h[0], l[0]); split_bf16(v.y, h[1], l[1]);
            split_bf16(v.z, h[2], l[2]); split_bf16(v.w, h[3], l[3]);
            int o = tok * APAD + dq * 4;
            *(uint2*)&ah[o] = make_uint2((u32)h[0] | ((u32)h[1] << 16), (u32)h[2] | ((u32)h[3] << 16));
            *(uint2*)&al[o] = make_uint2((u32)l[0] | ((u32)l[1] << 16), (u32)l[2] | ((u32)l[3] << 16));
        }
    }
    __syncthreads();

    u32 aoff = (u32)((wm * 16 + (lane & 15)) * (APAD * 2) + (lane >> 4) * 16);
    u32 Ah[8][4], Al[8][4];
    #pragma unroll
    for (int ks = 0; ks < 8; ++ks) {
        ldsm4(Ah[ks], sbase + OFF_AHI + aoff + ks * 32);
        ldsm4(Al[ks], sbase + OFF_ALO + aoff + ks * 32);
    }

    float accF[4][4];
    #pragma unroll
    for (int nt = 0; nt < 4; ++nt)
        #pragma unroll
        for (int j = 0; j < 4; ++j) accF[nt][j] = 0.f;

    int rb = wm * 16 + (lane >> 2);
    int cb = wn * 32 + 2 * (lane & 3);

    for (int mi = 0; mi < NMG; ++mi) {
        int s = mi & 1;
        if (mi + 1 < NMG) {
            const char* src = (const char*)g_Bpk + (size_t)(m0 + mi + 1) * 65536;
            u32 dst = sbase + OFF_W + (s ^ 1) * 65536;
            #pragma unroll
            for (int r = 0; r < 8; ++r) {
                int idx = tid + r * 512;
                cp16(dst + idx * 16, src + (size_t)idx * 16);
            }
            asm volatile("cp.async.commit_group;" ::: "memory");
            asm volatile("cp.async.wait_group 1;" ::: "memory");
        } else {
            asm volatile("cp.async.wait_group 0;" ::: "memory");
        }
        __syncthreads();

        float accY[4][4];
        #pragma unroll
        for (int nt = 0; nt < 4; ++nt)
            #pragma unroll
            for (int j = 0; j < 4; ++j) accY[nt][j] = 0.f;

        u32 wbase = sbase + OFF_W + s * 65536;
        #pragma unroll
        for (int ks = 0; ks < 8; ++ks) {
            u32 b4[4][4];
            #pragma unroll
            for (int nt = 0; nt < 4; ++nt)
                lds128(b4[nt], wbase + (((ks * 16) + wn * 4 + nt) * 32 + lane) * 16);
            #pragma unroll
            for (int nt = 0; nt < 4; ++nt) mma_bf16(accY[nt], Ah[ks], b4[nt]);
            #pragma unroll
            for (int nt = 0; nt < 4; ++nt) mma_bf16(accY[nt], Ah[ks], b4[nt] + 2);
            #pragma unroll
            for (int nt = 0; nt < 4; ++nt) mma_bf16(accY[nt], Al[ks], b4[nt]);
        }

        float c0 = cs_s[mi * 64 + rb];
        float c1 = cs_s[mi * 64 + rb + 8];
        #pragma unroll
        for (int nt = 0; nt < 4; ++nt) {
            float2 bb = *(const float2*)&bct_s[mi * 128 + cb + nt * 8];
            accF[nt][0] = fmaf(c0, accY[nt][0] + bb.x, accF[nt][0]);
            accF[nt][1] = fmaf(c0, accY[nt][1] + bb.y, accF[nt][1]);
            accF[nt][2] = fmaf(c1, accY[nt][2] + bb.x, accF[nt][2]);
            accF[nt][3] = fmaf(c1, accY[nt][3] + bb.y, accF[nt][3]);
        }
        __syncthreads();
    }

    float* part = g_part + (size_t)blockIdx.y * T_TOK * DD;
    #pragma unroll
    for (int nt = 0; nt < 4; ++nt) {
        int col = cb + nt * 8;
        *(float2*)&part[(size_t)(t0 + rb) * DD + col]     = make_float2(accF[nt][0], accF[nt][1]);
        *(float2*)&part[(size_t)(t0 + rb + 8) * DD + col] = make_float2(accF[nt][2], accF[nt][3]);
    }
}

// ---------------- kd: combine GROUPS partials ----------------------------------
__global__ void __launch_bounds__(256) kd_combine(float* __restrict__ out)
{
    int i = blockIdx.x * 256 + threadIdx.x;
    float4 r = make_float4(0.f, 0.f, 0.f, 0.f);
    #pragma unroll
    for (int g = 0; g < GROUPS; ++g) {
        float4 a = ((const float4*)(g_part + (size_t)g * T_TOK * DD))[i];
        r.x += a.x; r.y += a.y; r.z += a.z; r.w += a.w;
    }
    ((float4*)out)[i] = r;
}

// ---------------- launch ------------------------------------------------------
extern "C" void kernel_launch(void* const* d_in, const int* in_sizes, int n_in,
                              void* d_out, int out_size)
{
    const float* x    = (const float*)d_in[0];
    const float* ctx  = (const float*)d_in[1];
    const float* Wt   = (const float*)d_in[2];
    const float* bt   = (const float*)d_in[3];
    const float* chr  = (const float*)d_in[4];
    const float* Wg   = (const float*)d_in[5];
    const float* bg   = (const float*)d_in[6];
    const float* Wv   = (const float*)d_in[7];
    const float* bv   = (const float*)d_in[8];
    const float* O    = (const float*)d_in[9];
    const float* W1   = (const float*)d_in[10];
    const float* b1   = (const float*)d_in[11];
    const float* W2   = (const float*)d_in[12];
    const float* b2   = (const float*)d_in[13];
    const float* Wi   = (const float*)d_in[14];
    const float* bi   = (const float*)d_in[15];
    float* out = (float*)d_out;

    cudaFuncSetAttribute(kc_mma, cudaFuncAttributeMaxDynamicSharedMemorySize, SMEM_KC);
    cudaFuncSetAttribute(kb1_mma, cudaFuncAttributeMaxDynamicSharedMemorySize, SMEM_KB1);
    cudaFuncSetAttribute(kb2_sel, cudaFuncAttributeMaxDynamicSharedMemorySize, SMEM_KB2);

    ka1<<<64, 128>>>(Wt, bt, chr, Wv, bv);
    ka2<<<520, 128>>>(Wt, Wi, bi);
    ka3<<<384, 128>>>(W1, Wg);
    kb1_mma<<<dim3(T_TOK / 32, 2), 256, SMEM_KB1>>>(x, ctx, b1, bg);
    kb2_sel<<<T_TOK / 64, 512, SMEM_KB2>>>(W2, b2, O, out);
    kc_mma<<<dim3(T_TOK / 64, GROUPS), 512, SMEM_KC>>>(x);
    kd_combine<<<(T_TOK * DD / 4) / 256, 256>>>(out);
}

// round 17
// speedup vs baseline: 1.4849x; 1.3033x over previous
#include <cuda_runtime.h>
#include <cuda_bf16.h>
#include <cuda_fp16.h>
#include <math.h>

#define T_TOK 8192
#define DD    128
#define MM    64
#define GROUPS 5
#define NMG   13          // mechanisms per group (5*13 = 65)

typedef unsigned long long ull;
typedef unsigned int u32;
typedef unsigned short u16;

// ---------------- scratch ----------------------------------------------------
__device__ float g_cbuf[T_TOK * MM];        // c[t][m]
__device__ float g_uT[DD * MM];             // [d][m]
__device__ float g_bveff[MM];
__device__ float g_bc[MM * DD];             // bt + char
__device__ float g_bct[65 * DD];            // bctil[m] ; m=64 -> bi
__device__ u32   g_Bpk[65 * 8192];          // kc W frag-packed fp16 single: [m][ks][nt][lane][w0,w1]
__device__ u32   g_W1pk[16 * 48 * 32 * 4];  // kb extended-W frag-packed bf16 hi/lo (384 cols)
__device__ float g_hta[(size_t)T_TOK * 384];// kb1 output: gelu(h) | timing | victory
__device__ float g_part[GROUPS * T_TOK * DD];

// ---------------- helpers ------------------------------------------------------
__device__ __forceinline__ u32 smem_u32(const void* p) {
    u32 a;
    asm("{ .reg .u64 t; cvta.to.shared.u64 t, %1; cvt.u32.u64 %0, t; }" : "=r"(a) : "l"(p));
    return a;
}
__device__ __forceinline__ void mma_bf16(float* c, const u32* a, const u32* b) {
    asm volatile("mma.sync.aligned.m16n8k16.row.col.f32.bf16.bf16.f32 "
        "{%0,%1,%2,%3}, {%4,%5,%6,%7}, {%8,%9}, {%0,%1,%2,%3};"
        : "+f"(c[0]), "+f"(c[1]), "+f"(c[2]), "+f"(c[3])
        : "r"(a[0]), "r"(a[1]), "r"(a[2]), "r"(a[3]), "r"(b[0]), "r"(b[1]));
}
__device__ __forceinline__ void mma_f16(float* c, const u32* a, const u32* b) {
    asm volatile("mma.sync.aligned.m16n8k16.row.col.f32.f16.f16.f32 "
        "{%0,%1,%2,%3}, {%4,%5,%6,%7}, {%8,%9}, {%0,%1,%2,%3};"
        : "+f"(c[0]), "+f"(c[1]), "+f"(c[2]), "+f"(c[3])
        : "r"(a[0]), "r"(a[1]), "r"(a[2]), "r"(a[3]), "r"(b[0]), "r"(b[1]));
}
__device__ __forceinline__ void ldsm4(u32* r, u32 addr) {
    asm volatile("ldmatrix.sync.aligned.m8n8.x4.shared.b16 {%0,%1,%2,%3}, [%4];"
        : "=r"(r[0]), "=r"(r[1]), "=r"(r[2]), "=r"(r[3]) : "r"(addr));
}
__device__ __forceinline__ void lds128(u32* r, u32 addr) {
    asm volatile("ld.shared.v4.u32 {%0,%1,%2,%3}, [%4];"
        : "=r"(r[0]), "=r"(r[1]), "=r"(r[2]), "=r"(r[3]) : "r"(addr));
}
__device__ __forceinline__ void lds64(u32* r, u32 addr) {
    asm volatile("ld.shared.v2.u32 {%0,%1}, [%2];"
        : "=r"(r[0]), "=r"(r[1]) : "r"(addr));
}
__device__ __forceinline__ void cp16(u32 dst, const void* src) {
    asm volatile("cp.async.cg.shared.global [%0], [%1], 16;" :: "r"(dst), "l"(src) : "memory");
}
__device__ __forceinline__ void split_bf16(float v, u16& h, u16& l) {
    __nv_bfloat16 hb = __float2bfloat16_rn(v);
    float r = v - __bfloat162float(hb);
    h = __bfloat16_as_ushort(hb);
    l = __bfloat16_as_ushort(__float2bfloat16_rn(r));
}
__device__ __forceinline__ void split_f16(float v, u16& h, u16& l) {
    __half hb = __float2half_rn(v);
    float r = v - __half2float(hb);
    h = __half_as_ushort(hb);
    l = __half_as_ushort(__float2half_rn(r));
}

// ---------------- ka1: bc, bveff, uT --------------------------------------------
__global__ void __launch_bounds__(128) ka1(
    const float* __restrict__ Wt, const float* __restrict__ bt,
    const float* __restrict__ chr,
    const float* __restrict__ Wv, const float* __restrict__ bv)
{
    int m = blockIdx.x, tid = threadIdx.x;
    int lane = tid & 31, warp = tid >> 5;
    __shared__ float red[4];

    float wv  = Wv[m * DD + tid];
    float bcv = bt[m * DD + tid] + chr[m * DD + tid];
    g_bc[m * DD + tid]  = bcv;

    float v = bcv * wv;
    #pragma unroll
    for (int o = 16; o > 0; o >>= 1) v += __shfl_down_sync(0xffffffffu, v, o);
    if (lane == 0) red[warp] = v;
    __syncthreads();
    if (tid == 0) g_bveff[m] = bv[m] + red[0] + red[1] + red[2] + red[3];

    const float4* W4 = (const float4*)Wt + (size_t)m * 4096;
    float4 wv4 = ((const float4*)(Wv + m * DD))[lane];
    for (int r = warp; r < DD; r += 8) {
        float4 w0 = W4[r * 32 + lane];
        float4 w1 = W4[(r + 4) * 32 + lane];
        float a0 = w0.x * wv4.x + w0.y * wv4.y + w0.z * wv4.z + w0.w * wv4.w;
        float a1 = w1.x * wv4.x + w1.y * wv4.y + w1.z * wv4.z + w1.w * wv4.w;
        #pragma unroll
        for (int o = 16; o > 0; o >>= 1) {
            a0 += __shfl_down_sync(0xffffffffu, a0, o);
            a1 += __shfl_down_sync(0xffffffffu, a1, o);
        }
        if (lane == 0) {
            g_uT[r * MM + m]       = a0;
            g_uT[(r + 4) * MM + m] = a1;
        }
    }
}

// ---------------- ka2: Wtil = Wt@Wi_bot -> fragment-packed fp16 single ----------
// grid 520: m = bid>>3, dq = bid&7 (16 d-rows per block)
__global__ void __launch_bounds__(128) ka2(
    const float* __restrict__ Wt, const float* __restrict__ Wi,
    const float* __restrict__ bi)
{
    int bid = blockIdx.x;
    int m = bid >> 3, dq = bid & 7, j = threadIdx.x;   // j = e
    u32* buf = g_Bpk + (size_t)m * 8192;

    float acc[16];

    if (m == 64) {   // Wi_top: B(e,d) = Wi[d][e]
        #pragma unroll 4
        for (int dd = 0; dd < 16; ++dd)
            acc[dd] = Wi[(dq * 16 + dd) * DD + j];
        if (dq == 0) g_bct[64 * DD + j] = bi[j];
    } else {
        __shared__ float ws[17][129];
        #pragma unroll
        for (int k = 0; k < 16; ++k) {
            int idx = j + k * 128;
            int d = idx >> 7, e = idx & 127;
            ws[d][e] = Wt[(size_t)(m * DD + dq * 16 + d) * DD + e];
        }
        if (dq == 0) ws[16][j] = g_bc[m * DD + j];
        __syncthreads();

        #pragma unroll
        for (int d = 0; d < 16; ++d) acc[d] = 0.f;
        float accb = 0.f;
        for (int e = 0; e < 128; ++e) {
            float wi = Wi[(128 + e) * DD + j];
            #pragma unroll
            for (int d = 0; d < 16; ++d) acc[d] = fmaf(ws[d][e], wi, acc[d]);
            if (dq == 0) accb = fmaf(ws[16][e], wi, accb);
        }
        if (dq == 0) g_bct[m * DD + j] = accb;
    }

    int ntile = j >> 3;
    #pragma unroll
    for (int dd = 0; dd < 16; dd += 2) {
        int d = dq * 16 + dd;
        u16 p0 = __half_as_ushort(__float2half_rn(acc[dd]));
        u16 p1 = __half_as_ushort(__float2half_rn(acc[dd + 1]));
        u32 w = (u32)p0 | ((u32)p1 << 16);
        int lane = (j & 7) * 4 + ((d & 7) >> 1);
        int ks = d >> 4;
        int rh = (d >> 3) & 1;
        u32* v = buf + (((ks * 16) + ntile) * 32 + lane) * 2;
        v[rh] = w;
    }
}

// ---------------- ka3: pack extended W1 [256k x 384n] into bf16 hi/lo frags -----
__global__ void __launch_bounds__(128) ka3(
    const float* __restrict__ W1, const float* __restrict__ Wg)
{
    int j = blockIdx.x;        // col 0..383
    int t = threadIdx.x;       // handles k = 2t, 2t+1
    float v0, v1;
    if (j < 256)      { v0 = W1[(2 * t) * 256 + j]; v1 = W1[(2 * t + 1) * 256 + j]; }
    else if (j < 320) {
        int g = j - 256;
        v0 = (t < 64) ? Wg[g * DD + 2 * t]     : 0.f;
        v1 = (t < 64) ? Wg[g * DD + 2 * t + 1] : 0.f;
    } else {
        int g = j - 320;
        v0 = (t < 64) ? g_uT[(2 * t) * MM + g]     : 0.f;
        v1 = (t < 64) ? g_uT[(2 * t + 1) * MM + g] : 0.f;
    }
    u16 h0, l0, h1, l1;
    split_bf16(v0, h0, l0);
    split_bf16(v1, h1, l1);
    u32 hw = (u32)h0 | ((u32)h1 << 16);
    u32 lw = (u32)l0 | ((u32)l1 << 16);
    int lane = (j & 7) * 4 + (t & 3);
    int ks = t >> 3;
    int rh = (t >> 2) & 1;
    int nt = j >> 3;
    u32* v = g_W1pk + (((ks * 48) + nt) * 32 + lane) * 4;
    v[rh]     = hw;
    v[2 + rh] = lw;
}

// ---------------- kb1: extended MMA (h|ta|va), activation, -> g_hta -------------
#define KB1_A    0                       // A hi (32 x 528B) then lo
#define KB1_ALO  16896
#define KB1_B    33792                   // 2 stages x 12288
#define KB1_BIAS 58368                   // 384 x 4
#define SMEM_KB1 59904

__global__ void __launch_bounds__(256, 2) kb1_mma(
    const float* __restrict__ x, const float* __restrict__ ctx,
    const float* __restrict__ b1, const float* __restrict__ bg)
{
    extern __shared__ __align__(16) char smem[];
    u32 sbase = smem_u32(smem);
    int tid  = threadIdx.x;
    int lane = tid & 31, wid = tid >> 5;
    int wm = wid & 1, wn = wid >> 1;
    int t0 = blockIdx.x * 32;
    int nh = blockIdx.y;                 // n-half: n-tiles nh*24 .. nh*24+23

    {
        #pragma unroll
        for (int r = 0; r < 3; ++r) {
            int idx = tid + r * 256;
            const char* src = (const char*)g_W1pk
                + ((size_t)((0 * 48) + nh * 24 + (idx >> 5)) * 32 + (idx & 31)) * 16;
            cp16(sbase + KB1_B + idx * 16, src);
        }
        asm volatile("cp.async.commit_group;" ::: "memory");
    }

    {
        u16* ah = (u16*)(smem + KB1_A);
        u16* al = (u16*)(smem + KB1_ALO);
        #pragma unroll
        for (int r = 0; r < 8; ++r) {
            int idx = tid + r * 256;
            int tok = idx >> 6, cq = idx & 63;
            float4 v = (cq < 32) ? ((const float4*)(x   + (size_t)(t0 + tok) * DD))[cq]
                                 : ((const float4*)(ctx + (size_t)(t0 + tok) * DD))[cq - 32];
            u16 h[4], l[4];
            split_bf16(v.x, h[0], l[0]); split_bf16(v.y, h[1], l[1]);
            split_bf16(v.z, h[2], l[2]); split_bf16(v.w, h[3], l[3]);
            int o = tok * 264 + cq * 4;
            *(uint2*)&ah[o] = make_uint2((u32)h[0] | ((u32)h[1] << 16), (u32)h[2] | ((u32)h[3] << 16));
            *(uint2*)&al[o] = make_uint2((u32)l[0] | ((u32)l[1] << 16), (u32)l[2] | ((u32)l[3] << 16));
        }
    }

    float* bias = (float*)(smem + KB1_BIAS);
    for (int i = tid; i < 384; i += 256) {
        float b;
        if (i < 256)      b = b1[i];
        else if (i < 320) b = bg[i - 256];
        else              b = g_bveff[i - 320];
        bias[i] = b;
    }
    __syncthreads();

    float accY[6][4];
    #pragma unroll
    for (int t = 0; t < 6; ++t)
        #pragma unroll
        for (int q = 0; q < 4; ++q) accY[t][q] = 0.f;

    u32 abyte = (u32)((wm * 16 + (lane & 15)) * 528 + (lane >> 4) * 16);

    for (int ks = 0; ks < 16; ++ks) {
        int s = ks & 1;
        if (ks < 15) {
            u32 dst = sbase + KB1_B + (s ^ 1) * 12288;
            #pragma unroll
            for (int r = 0; r < 3; ++r) {
                int idx = tid + r * 256;
                const char* src = (const char*)g_W1pk
                    + ((size_t)(((ks + 1) * 48) + nh * 24 + (idx >> 5)) * 32 + (idx & 31)) * 16;
                cp16(dst + idx * 16, src);
            }
            asm volatile("cp.async.commit_group;" ::: "memory");
            asm volatile("cp.async.wait_group 1;" ::: "memory");
        } else {
            asm volatile("cp.async.wait_group 0;" ::: "memory");
        }
        __syncthreads();

        u32 ahf[4], alf[4];
        ldsm4(ahf, sbase + KB1_A + abyte + ks * 32);
        ldsm4(alf, sbase + KB1_ALO + abyte + ks * 32);
        u32 bb = sbase + KB1_B + s * 12288;
        #pragma unroll
        for (int t = 0; t < 6; ++t) {
            u32 b4[4];
            lds128(b4, bb + (u32)(((wn * 6 + t) * 32 + lane) * 16));
            mma_bf16(accY[t], ahf, b4);
            mma_bf16(accY[t], ahf, b4 + 2);
            mma_bf16(accY[t], alf, b4);
        }
        __syncthreads();
    }

    int rb = wm * 16 + (lane >> 2);
    #pragma unroll
    for (int t = 0; t < 6; ++t) {
        int col = (nh * 24 + wn * 6 + t) * 8 + 2 * (lane & 3);
        float b0 = bias[col], b1v = bias[col + 1];
        float v00 = accY[t][0] + b0, v01 = accY[t][1] + b1v;
        float v10 = accY[t][2] + b0, v11 = accY[t][3] + b1v;
        if (col < 256) {
            v00 = 0.5f * v00 * (1.0f + erff(v00 * 0.70710678118654752f));
            v01 = 0.5f * v01 * (1.0f + erff(v01 * 0.70710678118654752f));
            v10 = 0.5f * v10 * (1.0f + erff(v10 * 0.70710678118654752f));
            v11 = 0.5f * v11 * (1.0f + erff(v11 * 0.70710678118654752f));
        } else {
            v00 = 1.0f / (1.0f + expf(-v00));
            v01 = 1.0f / (1.0f + expf(-v01));
            v10 = 1.0f / (1.0f + expf(-v10));
            v11 = 1.0f / (1.0f + expf(-v11));
        }
        *(float2*)&g_hta[(size_t)(t0 + rb) * 384 + col]     = make_float2(v00, v01);
        *(float2*)&g_hta[(size_t)(t0 + rb + 8) * 384 + col] = make_float2(v10, v11);
    }
}

// ---------------- kb2: 64-token CTAs; W2+O staged once; softmax over 64 threads -
#define KB2_W2   0                       // 64 KB
#define KB2_O    65536                   // 16 KB
#define KB2_H    81920                   // 64 x 260 fp32 = 66560
#define KB2_LS   148480                  // 64 x 68 fp32 = 17408
#define KB2_VS   165888                  // 17408
#define SMEM_KB2 183296

__global__ void __launch_bounds__(512) kb2_sel(
    const float* __restrict__ W2, const float* __restrict__ b2,
    const float* __restrict__ O,  float* __restrict__ out)
{
    extern __shared__ __align__(16) char smem[];
    u32 sbase = smem_u32(smem);
    float* w2s = (float*)(smem + KB2_W2);
    float* os  = (float*)(smem + KB2_O);
    float* hsm = (float*)(smem + KB2_H);
    float* ls  = (float*)(smem + KB2_LS);
    float* vs  = (float*)(smem + KB2_VS);

    int t0 = blockIdx.x * 64;
    int tid = threadIdx.x;

    #pragma unroll
    for (int r = 0; r < 8; ++r) {
        int idx = tid + r * 512;
        cp16(sbase + KB2_W2 + idx * 16, (const char*)W2 + (size_t)idx * 16);
    }
    #pragma unroll
    for (int r = 0; r < 2; ++r) {
        int idx = tid + r * 512;
        cp16(sbase + KB2_O + idx * 16, (const char*)O + (size_t)idx * 16);
    }
    #pragma unroll
    for (int r = 0; r < 8; ++r) {
        int idx = tid + r * 512;            // 0..4095
        int tok = idx >> 6, cq = idx & 63;
        cp16(sbase + KB2_H + tok * 1040 + cq * 16,
             (const char*)(g_hta + (size_t)(t0 + tok) * 384 + cq * 4));
    }
    asm volatile("cp.async.commit_group;" ::: "memory");
    asm volatile("cp.async.wait_group 0;" ::: "memory");
    __syncthreads();

    int n  = tid & 63;
    int tg = tid >> 6;          // 8 token groups x 8 tokens

    {
        float acc[8];
        float bn = b2[n];
        #pragma unroll
        for (int q = 0; q < 8; ++q) acc[q] = bn;
        for (int j = 0; j < 256; j += 4) {
            float w0 = w2s[j * 64 + n];
            float w1 = w2s[(j + 1) * 64 + n];
            float w2v = w2s[(j + 2) * 64 + n];
            float w3 = w2s[(j + 3) * 64 + n];
            #pragma unroll
            for (int q = 0; q < 8; ++q) {
                float4 h4 = *(const float4*)&hsm[(tg * 8 + q) * 260 + j];
                acc[q] = fmaf(h4.x, w0, acc[q]);
                acc[q] = fmaf(h4.y, w1, acc[q]);
                acc[q] = fmaf(h4.z, w2v, acc[q]);
                acc[q] = fmaf(h4.w, w3, acc[q]);
            }
        }
        #pragma unroll
        for (int q = 0; q < 8; ++q) ls[(tg * 8 + q) * 68 + n] = acc[q];
    }
    __syncthreads();

    if (tid < 64) {
        float* row = ls + tid * 68;
        float mx = -1e30f;
        #pragma unroll
        for (int k = 0; k < 64; ++k) mx = fmaxf(mx, row[k]);
        float s = 0.f;
        #pragma unroll
        for (int k = 0; k < 64; ++k) { float e = expf(row[k] - mx); row[k] = e; s += e; }
        float inv = 1.0f / s;
        #pragma unroll
        for (int k = 0; k < 64; ++k) row[k] *= inv;
    }
    __syncthreads();

    {
        float gl[8];
        #pragma unroll
        for (int q = 0; q < 8; ++q) gl[q] = 0.f;
        for (int mm = 0; mm < 64; ++mm) {
            float o = os[mm * 64 + n];
            #pragma unroll
            for (int q = 0; q < 8; ++q)
                gl[q] = fmaf(ls[(tg * 8 + q) * 68 + mm], o, gl[q]);
        }
        #pragma unroll
        for (int q = 0; q < 8; ++q) {
            int tok = tg * 8 + q;
            float sc     = ls[tok * 68 + n];
            float timing = g_hta[(size_t)(t0 + tok) * 384 + 256 + n];
            float vic    = g_hta[(size_t)(t0 + tok) * 384 + 320 + n];
            float gate   = 1.0f + tanhf(gl[q]);
            g_cbuf[(size_t)(t0 + tok) * MM + n] = timing * gate * sc;
            vs[tok * 68 + n] = vic * sc;
        }
    }
    __syncthreads();

    if (tid < 64) {
        float s = 0.f;
        #pragma unroll
        for (int k = 0; k < 64; ++k) s += vs[tid * 68 + k];
        out[(size_t)T_TOK * DD + t0 + tid] = s;
    }
}

// ---------------- kc: fp16 2-pass fused GEMM (x split f16, W single f16) --------
#define APAD     136
#define OFF_W    0                        // 2 stages x 32768
#define OFF_AHI  65536                    // 64 x 272B = 17408
#define OFF_ALO  82944
#define OFF_CS   100352                   // 3328
#define OFF_BCT  103680                   // 6656
#define SMEM_KC  110336

__global__ void __launch_bounds__(512, 1) kc_mma(const float* __restrict__ x)
{
    extern __shared__ __align__(16) char smem[];
    u32 sbase = smem_u32(smem);
    float* cs_s  = (float*)(smem + OFF_CS);
    float* bct_s = (float*)(smem + OFF_BCT);

    int tid  = threadIdx.x;
    int lane = tid & 31, wid = tid >> 5;
    int wm = wid & 3, wn = wid >> 2;
    int t0 = blockIdx.x * 64;
    int m0 = blockIdx.y * NMG;

    for (int i = tid; i < NMG * 64; i += 512) {
        int mi = i >> 6, r = i & 63;
        int gm = m0 + mi;
        cs_s[i] = (gm == 64) ? 1.0f : g_cbuf[(size_t)(t0 + r) * MM + gm];
    }
    for (int i = tid; i < NMG * 128; i += 512) {
        int mi = i >> 7, r = i & 127;
        bct_s[i] = g_bct[(m0 + mi) * DD + r];
    }

    // prefetch W[m0] into stage 0 (32 KB)
    {
        const char* src = (const char*)g_Bpk + (size_t)m0 * 32768;
        #pragma unroll
        for (int r = 0; r < 4; ++r) {
            int idx = tid + r * 512;
            cp16(sbase + OFF_W + idx * 16, src + (size_t)idx * 16);
        }
        asm volatile("cp.async.commit_group;" ::: "memory");
    }

    // A: x split to fp16 hi/lo in smem (padded rows)
    {
        u16* ah = (u16*)(smem + OFF_AHI);
        u16* al = (u16*)(smem + OFF_ALO);
        #pragma unroll
        for (int r = 0; r < 4; ++r) {
            int idx = tid + r * 512;
            int tok = idx >> 5, dq = idx & 31;
            float4 v = ((const float4*)(x + (size_t)(t0 + tok) * DD))[dq];
            u16 h[4], l[4];
            split_f16(v.x, h[0], l[0]); split_f16(v.y, h[1], l[1]);
            split_f16(v.z, h[2], l[2]); split_f16(v.w, h[3], l[3]);
            int o = tok * APAD + dq * 4;
            *(uint2*)&ah[o] = make_uint2((u32)h[0] | ((u32)h[1] << 16), (u32)h[2] | ((u32)h[3] << 16));
            *(uint2*)&al[o] = make_uint2((u32)l[0] | ((u32)l[1] << 16), (u32)l[2] | ((u32)l[3] << 16));
        }
    }
    __syncthreads();

    // hoist A fragments into registers (invariant across m)
    u32 aoff = (u32)((wm * 16 + (lane & 15)) * (APAD * 2) + (lane >> 4) * 16);
    u32 Ah[8][4], Al[8][4];
    #pragma unroll
    for (int ks = 0; ks < 8; ++ks) {
        ldsm4(Ah[ks], sbase + OFF_AHI + aoff + ks * 32);
        ldsm4(Al[ks], sbase + OFF_ALO + aoff + ks * 32);
    }

    float accF[4][4];
    #pragma unroll
    for (int nt = 0; nt < 4; ++nt)
        #pragma unroll
        for (int j = 0; j < 4; ++j) accF[nt][j] = 0.f;

    int rb = wm * 16 + (lane >> 2);
    int cb = wn * 32 + 2 * (lane & 3);

    for (int mi = 0; mi < NMG; ++mi) {
        int s = mi & 1;
        if (mi + 1 < NMG) {
            const char* src = (const char*)g_Bpk + (size_t)(m0 + mi + 1) * 32768;
            u32 dst = sbase + OFF_W + (s ^ 1) * 32768;
            #pragma unroll
            for (int r = 0; r < 4; ++r) {
                int idx = tid + r * 512;
                cp16(dst + idx * 16, src + (size_t)idx * 16);
            }
            asm volatile("cp.async.commit_group;" ::: "memory");
            asm volatile("cp.async.wait_group 1;" ::: "memory");
        } else {
            asm volatile("cp.async.wait_group 0;" ::: "memory");
        }
        __syncthreads();

        float accY[4][4];
        #pragma unroll
        for (int nt = 0; nt < 4; ++nt)
            #pragma unroll
            for (int j = 0; j < 4; ++j) accY[nt][j] = 0.f;

        u32 wbase = sbase + OFF_W + s * 32768;
        #pragma unroll
        for (int ks = 0; ks < 8; ++ks) {
            u32 b2r[4][2];
            #pragma unroll
            for (int nt = 0; nt < 4; ++nt)
                lds64(b2r[nt], wbase + (((ks * 16) + wn * 4 + nt) * 32 + lane) * 8);
            #pragma unroll
            for (int nt = 0; nt < 4; ++nt) mma_f16(accY[nt], Ah[ks], b2r[nt]);
            #pragma unroll
            for (int nt = 0; nt < 4; ++nt) mma_f16(accY[nt], Al[ks], b2r[nt]);
        }

        float c0 = cs_s[mi * 64 + rb];
        float c1 = cs_s[mi * 64 + rb + 8];
        #pragma unroll
        for (int nt = 0; nt < 4; ++nt) {
            float2 bb = *(const float2*)&bct_s[mi * 128 + cb + nt * 8];
            accF[nt][0] = fmaf(c0, accY[nt][0] + bb.x, accF[nt][0]);
            accF[nt][1] = fmaf(c0, accY[nt][1] + bb.y, accF[nt][1]);
            accF[nt][2] = fmaf(c1, accY[nt][2] + bb.x, accF[nt][2]);
            accF[nt][3] = fmaf(c1, accY[nt][3] + bb.y, accF[nt][3]);
        }
        __syncthreads();
    }

    float* part = g_part + (size_t)blockIdx.y * T_TOK * DD;
    #pragma unroll
    for (int nt = 0; nt < 4; ++nt) {
        int col = cb + nt * 8;
        *(float2*)&part[(size_t)(t0 + rb) * DD + col]     = make_float2(accF[nt][0], accF[nt][1]);
        *(float2*)&part[(size_t)(t0 + rb + 8) * DD + col] = make_float2(accF[nt][2], accF[nt][3]);
    }
}

// ---------------- kd: combine GROUPS partials ----------------------------------
__global__ void __launch_bounds__(256) kd_combine(float* __restrict__ out)
{
    int i = blockIdx.x * 256 + threadIdx.x;
    float4 r = make_float4(0.f, 0.f, 0.f, 0.f);
    #pragma unroll
    for (int g = 0; g < GROUPS; ++g) {
        float4 a = ((const float4*)(g_part + (size_t)g * T_TOK * DD))[i];
        r.x += a.x; r.y += a.y; r.z += a.z; r.w += a.w;
    }
    ((float4*)out)[i] = r;
}

// ---------------- launch ------------------------------------------------------
extern "C" void kernel_launch(void* const* d_in, const int* in_sizes, int n_in,
                              void* d_out, int out_size)
{
    const float* x    = (const float*)d_in[0];
    const float* ctx  = (const float*)d_in[1];
    const float* Wt   = (const float*)d_in[2];
    const float* bt   = (const float*)d_in[3];
    const float* chr  = (const float*)d_in[4];
    const float* Wg   = (const float*)d_in[5];
    const float* bg   = (const float*)d_in[6];
    const float* Wv   = (const float*)d_in[7];
    const float* bv   = (const float*)d_in[8];
    const float* O    = (const float*)d_in[9];
    const float* W1   = (const float*)d_in[10];
    const float* b1   = (const float*)d_in[11];
    const float* W2   = (const float*)d_in[12];
    const float* b2   = (const float*)d_in[13];
    const float* Wi   = (const float*)d_in[14];
    const float* bi   = (const float*)d_in[15];
    float* out = (float*)d_out;

    cudaFuncSetAttribute(kc_mma, cudaFuncAttributeMaxDynamicSharedMemorySize, SMEM_KC);
    cudaFuncSetAttribute(kb1_mma, cudaFuncAttributeMaxDynamicSharedMemorySize, SMEM_KB1);
    cudaFuncSetAttribute(kb2_sel, cudaFuncAttributeMaxDynamicSharedMemorySize, SMEM_KB2);

    ka1<<<64, 128>>>(Wt, bt, chr, Wv, bv);
    ka2<<<520, 128>>>(Wt, Wi, bi);
    ka3<<<384, 128>>>(W1, Wg);
    kb1_mma<<<dim3(T_TOK / 32, 2), 256, SMEM_KB1>>>(x, ctx, b1, bg);
    kb2_sel<<<T_TOK / 64, 512, SMEM_KB2>>>(W2, b2, O, out);
    kc_mma<<<dim3(T_TOK / 64, GROUPS), 512, SMEM_KC>>>(x);
    kd_combine<<<(T_TOK * DD / 4) / 256, 256>>>(out);
}